// round 15
// baseline (speedup 1.0000x reference)
#include <cuda_runtime.h>
#include <math.h>

#define BB 128
#define SS 16
#define EE 512
#define RR 1000
#define G3 1536
#define NSCALE 0.04419417382415922f

// ---- device scratch (static, no allocations) ----
__device__ float GI_emb[RR * G3];
__device__ float H1_emb[RR * EE];
__device__ float GHH_emb[RR * G3];
__device__ float g_Krel[RR * EE];
__device__ float g_KW[RR * EE];
__device__ float g_cs[RR];
__device__ float g_AT[EE * EE];
__device__ float g_wvec[EE];
__device__ float g_c0[1];

__device__ float g_gi [BB * SS * G3];
__device__ float g_h1 [BB * SS * EE];
__device__ float g_ghh[BB * SS * G3];

__device__ int   g_src [BB * SS];
__device__ int   g_ord [BB * SS];
__device__ int   g_sel [BB];
__device__ int   g_dslot[BB];
__device__ float g_pscore[BB * SS];

__device__ float g_pair [BB * EE];
__device__ float g_newh1[BB * EE];
__device__ float g_probp[BB * 1024];   // padded probs, [1000..1023] = 0
__device__ float g_pp[BB];             // prob of the pair key

// split-K partial buffers
__device__ float g_sc0[BB * RR];
__device__ float g_sc1[BB * RR];
__device__ float g_tv0[BB * EE];
__device__ float g_tv1[BB * EE];
__device__ float g_gp0[BB * G3];
__device__ float g_gp1[BB * G3];
__device__ float g_gm4[4][BB * G3];
__device__ float g_gh[4][BB * G3];

// phase-chaining counters (per round)
__device__ unsigned g_cnt1[16];
__device__ unsigned g_cnt2[16];
__device__ unsigned g_cnt3[16];
__device__ unsigned g_cnt4[16];

typedef unsigned long long ull;
__device__ __forceinline__ ull pack2(float lo, float hi) {
    ull r; asm("mov.b64 %0, {%1, %2};" : "=l"(r) : "f"(lo), "f"(hi)); return r;
}
__device__ __forceinline__ void unpack2(ull v, float& lo, float& hi) {
    asm("mov.b64 {%0, %1}, %2;" : "=f"(lo), "=f"(hi) : "l"(v));
}
#define FMA2(acc, a, b) asm("fma.rn.f32x2 %0, %1, %2, %0;" : "+l"(acc) : "l"(a), "l"(b))

__device__ __forceinline__ float sigmf(float x) { return 1.0f / (1.0f + expf(-x)); }

__device__ __forceinline__ const float* p_gi(int b, int s) {
    int src = g_src[b * SS + s];
    return (src >= 0) ? &GI_emb[(size_t)src * G3] : &g_gi[((size_t)b * SS + s) * G3];
}
__device__ __forceinline__ const float* p_ghh(int b, int s) {
    int src = g_src[b * SS + s];
    return (src >= 0) ? &GHH_emb[(size_t)src * G3] : &g_ghh[((size_t)b * SS + s) * G3];
}
__device__ __forceinline__ const float* p_h1(int b, int s) {
    int src = g_src[b * SS + s];
    return (src >= 0) ? &H1_emb[(size_t)src * EE] : &g_h1[((size_t)b * SS + s) * EE];
}

__global__ void k_init(const int* __restrict__ tokens) {
    int b = blockIdx.x, t = threadIdx.x;
    if (t < SS) {
        g_ord[b * SS + t] = t;
        g_src[b * SS + t] = tokens[b * SS + t];
    }
    if (b == 0 && t == 0) {
#pragma unroll
        for (int i = 0; i < 16; i++) {
            g_cnt1[i] = 0; g_cnt2[i] = 0; g_cnt3[i] = 0; g_cnt4[i] = 0;
        }
    }
}

// ---- flag-chain helpers ----
__device__ __forceinline__ void chain_signal(unsigned* c) {
    __threadfence();
    __syncthreads();
    if (threadIdx.x == 0) atomicAdd(c, 1u);
}
__device__ __forceinline__ void chain_wait(unsigned* c, unsigned target) {
    if (threadIdx.x == 0) {
        while (*(volatile unsigned*)c < target) __nanosleep(32);
        __threadfence();
    }
    __syncthreads();
}

// ======================================================================
// BEST-MEASURED core: 64x64 tile, 4x4 f32x2 reg tile, packed-A at use,
// ping-pong smem, one sync per k-tile.
// ======================================================================
struct PPBuf {
    float shA[2][16][68];
    float shB[2][16][68];
};

__device__ __forceinline__ void pp_storeA(float (*As)[68], int akg, int am, float4 ra) {
    As[akg*4+0][am] = ra.x; As[akg*4+1][am] = ra.y;
    As[akg*4+2][am] = ra.z; As[akg*4+3][am] = ra.w;
}
__device__ __forceinline__ void pp_compute(float (*As)[68], float (*Bs)[68],
                                           int tx, int ty, ull acc[4][2]) {
#pragma unroll
    for (int kk = 0; kk < 16; kk++) {
        ull b0 = *(const ull*)&Bs[kk][tx*4];
        ull b1 = *(const ull*)&Bs[kk][tx*4+2];
        float4 a = *(const float4*)&As[kk][ty*4];
        ull a0 = pack2(a.x, a.x), a1 = pack2(a.y, a.y);
        ull a2 = pack2(a.z, a.z), a3 = pack2(a.w, a.w);
        FMA2(acc[0][0], a0, b0); FMA2(acc[0][1], a0, b1);
        FMA2(acc[1][0], a1, b0); FMA2(acc[1][1], a1, b1);
        FMA2(acc[2][0], a2, b0); FMA2(acc[2][1], a2, b1);
        FMA2(acc[3][0], a3, b0); FMA2(acc[3][1], a3, b1);
    }
}

// Generic split-K GEMM job (identical math to R14's k_mm).
__device__ __forceinline__ void mm_job(
    const float* __restrict__ A, int lda,
    const float* __restrict__ W, int wld,
    float* __restrict__ out, int N,
    int kn, int kb, int NIT, int Kmax,
    int col0, int row0, PPBuf& tb)
{
    int t = threadIdx.x, tx = t & 15, ty = t >> 4;
    ull acc[4][2];
#pragma unroll
    for (int i = 0; i < 4; i++) { acc[i][0] = 0ULL; acc[i][1] = 0ULL; }

    int am = t >> 2, akg = t & 3;
    int gmA = row0 + am;
    int bn = t >> 2, bkg = t & 3;       // kn==0 (W is N-row-major)
    int kkB = t >> 4, ngB = t & 15;     // kn==1 (W is K-row-major)

    float4 ra = *(const float4*)&A[(size_t)gmA * lda + kb + akg * 4];
    float4 rb;
    if (kn == 0) {
        int gn = col0 + bn;
        rb = (gn < N) ? *(const float4*)&W[(size_t)gn * wld + kb + bkg * 4]
                      : make_float4(0.f, 0.f, 0.f, 0.f);
    } else {
        int k = kb + kkB;
        rb = (k < Kmax) ? *(const float4*)&W[(size_t)k * wld + col0 + ngB * 4]
                        : make_float4(0.f, 0.f, 0.f, 0.f);
    }
    pp_storeA(tb.shA[0], akg, am, ra);
    if (kn == 0) pp_storeA(tb.shB[0], bkg, bn, rb);
    else         *(float4*)&tb.shB[0][kkB][ngB * 4] = rb;
    __syncthreads();

    for (int it = 0; it < NIT; it++) {
        int cur = it & 1;
        if (it < NIT - 1) {
            int k0 = kb + (it + 1) * 16;
            ra = *(const float4*)&A[(size_t)gmA * lda + k0 + akg * 4];
            if (kn == 0) {
                int gn = col0 + bn;
                rb = (gn < N) ? *(const float4*)&W[(size_t)gn * wld + k0 + bkg * 4]
                              : make_float4(0.f, 0.f, 0.f, 0.f);
            } else {
                int k = k0 + kkB;
                rb = (k < Kmax) ? *(const float4*)&W[(size_t)k * wld + col0 + ngB * 4]
                                : make_float4(0.f, 0.f, 0.f, 0.f);
            }
        }
        pp_compute(tb.shA[cur], tb.shB[cur], tx, ty, acc);
        if (it < NIT - 1) {
            int nxt = 1 - cur;
            pp_storeA(tb.shA[nxt], akg, am, ra);
            if (kn == 0) pp_storeA(tb.shB[nxt], bkg, bn, rb);
            else         *(float4*)&tb.shB[nxt][kkB][ngB * 4] = rb;
        }
        __syncthreads();
    }
#pragma unroll
    for (int i = 0; i < 4; i++) {
        int gm = row0 + ty * 4 + i;
        float* orow = out + (size_t)gm * N;
#pragma unroll
        for (int j = 0; j < 2; j++) {
            float lo, hi;
            unpack2(acc[i][j], lo, hi);
            int c = col0 + tx * 4 + j * 2;
            if (c < N)     orow[c]     = lo;
            if (c + 1 < N) orow[c + 1] = hi;
        }
    }
}

// ============ init table GEMM (R14 proven): out = A@W^T*scale + bias
__global__ __launch_bounds__(256) void k_tab(
    const float* __restrict__ A, const float* __restrict__ W,
    const float* __restrict__ bias, float* __restrict__ out,
    int M, int N, int ldout, float scale)
{
    __shared__ PPBuf tb;
    int t = threadIdx.x, tx = t & 15, ty = t >> 4;
    int col0 = blockIdx.x * 64, row0 = blockIdx.y * 64;

    ull acc[4][2];
#pragma unroll
    for (int i = 0; i < 4; i++) { acc[i][0] = 0ULL; acc[i][1] = 0ULL; }

    int am = t >> 2, akg = t & 3;
    int gmA = row0 + am, gnB = col0 + am;

    float4 ra = (gmA < M) ? *(const float4*)&A[(size_t)gmA * 512 + akg * 4]
                          : make_float4(0.f, 0.f, 0.f, 0.f);
    float4 rb = (gnB < N) ? *(const float4*)&W[(size_t)gnB * 512 + akg * 4]
                          : make_float4(0.f, 0.f, 0.f, 0.f);
    pp_storeA(tb.shA[0], akg, am, ra);
    pp_storeA(tb.shB[0], akg, am, rb);
    __syncthreads();

    for (int it = 0; it < 32; it++) {
        int cur = it & 1;
        if (it < 31) {
            int k0 = (it + 1) * 16;
            ra = (gmA < M) ? *(const float4*)&A[(size_t)gmA * 512 + k0 + akg * 4]
                           : make_float4(0.f, 0.f, 0.f, 0.f);
            rb = (gnB < N) ? *(const float4*)&W[(size_t)gnB * 512 + k0 + akg * 4]
                           : make_float4(0.f, 0.f, 0.f, 0.f);
        }
        pp_compute(tb.shA[cur], tb.shB[cur], tx, ty, acc);
        if (it < 31) {
            int nxt = 1 - cur;
            pp_storeA(tb.shA[nxt], akg, am, ra);
            pp_storeA(tb.shB[nxt], akg, am, rb);
        }
        __syncthreads();
    }
#pragma unroll
    for (int i = 0; i < 4; i++) {
        int gm = row0 + ty * 4 + i;
        if (gm >= M) continue;
        float* orow = out + (size_t)gm * (size_t)ldout;
#pragma unroll
        for (int j = 0; j < 2; j++) {
            float lo, hi;
            unpack2(acc[i][j], lo, hi);
            int c = col0 + tx * 4 + j * 2;
            if (c < N)     orow[c]     = lo * scale + (bias ? bias[c]     : 0.f);
            if (c + 1 < N) orow[c + 1] = hi * scale + (bias ? bias[c + 1] : 0.f);
        }
    }
}

// ============ KW = Krel @ Wq (B K-row-major), init-only
__global__ __launch_bounds__(256) void k_gemm_kn(
    const float* __restrict__ A, const float* __restrict__ B,
    float* __restrict__ out, int M, int N, int ldb)
{
    __shared__ PPBuf tb;
    int t = threadIdx.x, tx = t & 15, ty = t >> 4;
    int col0 = blockIdx.x * 64, row0 = blockIdx.y * 64;
    ull acc[4][2];
#pragma unroll
    for (int i = 0; i < 4; i++) { acc[i][0] = 0ULL; acc[i][1] = 0ULL; }

    int am = t >> 2, akg = t & 3;
    int gmA = row0 + am;
    int kkB = t >> 4, ngB = t & 15;

    float4 ra = (gmA < M) ? *(const float4*)&A[(size_t)gmA * 512 + akg * 4]
                          : make_float4(0.f,0.f,0.f,0.f);
    float4 rb = *(const float4*)&B[(size_t)kkB * ldb + col0 + ngB * 4];
    pp_storeA(tb.shA[0], akg, am, ra);
    *(float4*)&tb.shB[0][kkB][ngB * 4] = rb;
    __syncthreads();

    for (int it = 0; it < 32; it++) {
        int cur = it & 1;
        if (it < 31) {
            int k0 = (it + 1) * 16;
            ra = (gmA < M) ? *(const float4*)&A[(size_t)gmA * 512 + k0 + akg * 4]
                           : make_float4(0.f,0.f,0.f,0.f);
            rb = *(const float4*)&B[(size_t)(k0 + kkB) * ldb + col0 + ngB * 4];
        }
        pp_compute(tb.shA[cur], tb.shB[cur], tx, ty, acc);
        if (it < 31) {
            int nxt = 1 - cur;
            pp_storeA(tb.shA[nxt], akg, am, ra);
            *(float4*)&tb.shB[nxt][kkB][ngB * 4] = rb;
        }
        __syncthreads();
    }
#pragma unroll
    for (int i = 0; i < 4; i++) {
        int gm = row0 + ty * 4 + i;
        if (gm >= M) continue;
#pragma unroll
        for (int j = 0; j < 2; j++) {
            float lo, hi;
            unpack2(acc[i][j], lo, hi);
            int c = col0 + tx * 4 + j * 2;
            if (c < N)     out[(size_t)gm * N + c]     = lo;
            if (c + 1 < N) out[(size_t)gm * N + c + 1] = hi;
        }
    }
}

// ============ AT[m][n] = sum_k Wk[k][m] * Wq[k][n]  (both K-row-major), init-only
__global__ __launch_bounds__(256) void k_gemm_tn(
    const float* __restrict__ P, const float* __restrict__ Q, float* __restrict__ out)
{
    __shared__ PPBuf tb;
    int t = threadIdx.x, tx = t & 15, ty = t >> 4;
    int col0 = blockIdx.x * 64, row0 = blockIdx.y * 64;
    ull acc[4][2];
#pragma unroll
    for (int i = 0; i < 4; i++) { acc[i][0] = 0ULL; acc[i][1] = 0ULL; }
    int kk0 = t >> 4, g = t & 15;

    float4 ra = *(const float4*)&P[(size_t)kk0 * 512 + row0 + g * 4];
    float4 rb = *(const float4*)&Q[(size_t)kk0 * 512 + col0 + g * 4];
    *(float4*)&tb.shA[0][kk0][g * 4] = ra;
    *(float4*)&tb.shB[0][kk0][g * 4] = rb;
    __syncthreads();

    for (int it = 0; it < 32; it++) {
        int cur = it & 1;
        if (it < 31) {
            int k0 = (it + 1) * 16;
            ra = *(const float4*)&P[(size_t)(k0 + kk0) * 512 + row0 + g * 4];
            rb = *(const float4*)&Q[(size_t)(k0 + kk0) * 512 + col0 + g * 4];
        }
        pp_compute(tb.shA[cur], tb.shB[cur], tx, ty, acc);
        if (it < 31) {
            int nxt = 1 - cur;
            *(float4*)&tb.shA[nxt][kk0][g * 4] = ra;
            *(float4*)&tb.shB[nxt][kk0][g * 4] = rb;
        }
        __syncthreads();
    }
#pragma unroll
    for (int i = 0; i < 4; i++) {
        int gm = row0 + ty * 4 + i;
#pragma unroll
        for (int j = 0; j < 2; j++) {
            float lo, hi;
            unpack2(acc[i][j], lo, hi);
            int c = col0 + tx * 4 + j * 2;
            out[(size_t)gm * 512 + c]     = lo;
            out[(size_t)gm * 512 + c + 1] = hi;
        }
    }
}

__global__ void k_wc(const float* __restrict__ Wq, const float* __restrict__ bq,
                     const float* __restrict__ Wk, const float* __restrict__ bk) {
    __shared__ float red[256];
    int t = threadIdx.x;
    int i = blockIdx.x * 256 + t;
    float acc = 0.f;
    for (int n = 0; n < EE; n++)
        acc += Wq[(size_t)n * EE + i] * bk[n] + Wk[(size_t)n * EE + i] * bq[n];
    g_wvec[i] = acc;
    if (blockIdx.x == 0) {
        float p = 0.f;
        for (int n = t; n < EE; n += 256) p += bq[n] * bk[n];
        red[t] = p; __syncthreads();
        for (int s = 128; s > 0; s >>= 1) { if (t < s) red[t] += red[t + s]; __syncthreads(); }
        if (t == 0) g_c0[0] = red[0];
    }
}

__global__ void k_h1emb(const float* __restrict__ b_hh) {
    int tk = blockIdx.x;
    const float* gi = &GI_emb[(size_t)tk * G3];
    for (int e = threadIdx.x; e < EE; e += blockDim.x) {
        float r = sigmf(gi[e] + b_hh[e]);
        float z = sigmf(gi[EE + e] + b_hh[EE + e]);
        float n = tanhf(gi[2 * EE + e] + r * b_hh[2 * EE + e]);
        H1_emb[(size_t)tk * EE + e] = (1.f - z) * n;
    }
}

__global__ void k_cinit(const float* __restrict__ bq) {
    int r = blockIdx.x * 8 + (threadIdx.x >> 5);
    int lane = threadIdx.x & 31;
    if (r >= RR) return;
    float s = 0.f;
    for (int e = lane; e < EE; e += 32) s += bq[e] * g_Krel[(size_t)r * EE + e];
#pragma unroll
    for (int off = 16; off > 0; off >>= 1) s += __shfl_down_sync(0xffffffffu, s, off);
    if (lane == 0) g_cs[r] = NSCALE * s;
}

// =================== round-phase device functions ===================

__device__ __forceinline__ float pair_elem(const float* gi, const float* gh,
                                           const float* h1, int e) {
    float r = sigmf(gi[e] + gh[e]);
    float z = sigmf(gi[EE + e] + gh[EE + e]);
    float n = tanhf(gi[2 * EE + e] + r * gh[2 * EE + e]);
    return (1.f - z) * n + z * h1[e];
}

struct SmSmall {
    float red[256];
    int sord[SS];
    float sps[SS];
    int sbestj;
};
union SmemU {
    PPBuf pp;
    SmSmall sm;
    float sgi[G3];
};

__device__ void ph_pairsel(int b, const float* __restrict__ wfc,
                           const float* __restrict__ bfc,
                           const float* __restrict__ b_hh,
                           int npairs, int zloss, float* __restrict__ loss_out,
                           int first, SmSmall& sm)
{
    int t = threadIdx.x;
    int w = t >> 5, lane = t & 31;

    if (!first) {
        int slot = g_dslot[b];
        float* orow = &g_ghh[((size_t)b * SS + slot) * G3];
        const float* gA = &g_gh[0][(size_t)b * G3];
        const float* gB = &g_gh[1][(size_t)b * G3];
        const float* gC = &g_gh[2][(size_t)b * G3];
        const float* gD = &g_gh[3][(size_t)b * G3];
        for (int e = t; e < G3; e += 256)
            orow[e] = gA[e] + gB[e] + gC[e] + gD[e] + b_hh[e];
        __syncthreads();
    }

    if (t < SS) {
        sm.sord[t] = g_ord[b * SS + t];
        sm.sps[t]  = g_pscore[b * SS + t];
    }
    int prev_sel = g_sel[b];
    __syncthreads();

    int j0 = -1, j1 = -1;
    if (first) {
        j0 = w;  j1 = w + 8;
        if (j0 >= npairs) j0 = -1;
        if (j1 >= npairs) j1 = -1;
    } else {
        int cnt = 0, jj[2];
        if (prev_sel - 1 >= 0 && prev_sel - 1 < npairs) jj[cnt++] = prev_sel - 1;
        if (prev_sel >= 0 && prev_sel < npairs)         jj[cnt++] = prev_sel;
        if (w < cnt) j0 = jj[w];
    }
#pragma unroll
    for (int rep = 0; rep < 2; rep++) {
        int j = (rep == 0) ? j0 : j1;
        if (j >= 0) {
            const float* gi = p_gi(b, sm.sord[j + 1]);
            const float* gh = p_ghh(b, sm.sord[j]);
            const float* h1 = p_h1(b, sm.sord[j]);
            float s = 0.f;
            for (int e = lane; e < EE; e += 32)
                s += pair_elem(gi, gh, h1, e) * wfc[e];
#pragma unroll
            for (int off = 16; off > 0; off >>= 1)
                s += __shfl_down_sync(0xffffffffu, s, off);
            if (lane == 0) {
                float sc = sigmf(s + bfc[0]);
                sm.sps[j] = sc;
                g_pscore[b * SS + j] = sc;
            }
        }
    }
    __syncthreads();

    if (t == 0) {
        int bj = 0; float bs = sm.sps[0];
        for (int j = 1; j < npairs; j++)
            if (sm.sps[j] > bs) { bs = sm.sps[j]; bj = j; }
        sm.sbestj = bj;
        g_sel[b] = bj;
        if (zloss >= 0) loss_out[b * SS + zloss] = 0.f;
    }
    __syncthreads();
    int j = sm.sbestj;
    const float* gi = p_gi(b, sm.sord[j + 1]);
    const float* gh = p_ghh(b, sm.sord[j]);
    const float* h1 = p_h1(b, sm.sord[j]);
    for (int e = t; e < EE; e += 256)
        g_pair[(size_t)b * EE + e] = pair_elem(gi, gh, h1, e);
}

__device__ __forceinline__ float bsum(float v, float* red, int t) {
    red[t] = v; __syncthreads();
    for (int s = 128; s > 0; s >>= 1) { if (t < s) red[t] += red[t + s]; __syncthreads(); }
    return red[0];
}
__device__ __forceinline__ float bmax(float v, float* red, int t) {
    red[t] = v; __syncthreads();
    for (int s = 128; s > 0; s >>= 1) { if (t < s) red[t] = fmaxf(red[t], red[t + s]); __syncthreads(); }
    return red[0];
}

__device__ void ph_softmax(int b, int lossidx, int L, int do_book,
                           float* __restrict__ loss_out,
                           float* __restrict__ scores_out, float* red)
{
    int t = threadIdx.x;
    const float* pp  = &g_pair[(size_t)b * EE];
    const float* tv0 = &g_tv0[(size_t)b * EE];
    const float* tv1 = &g_tv1[(size_t)b * EE];
    const float* s0  = &g_sc0[(size_t)b * RR];
    const float* s1  = &g_sc1[(size_t)b * RR];

    float part = 0.f;
    for (int e = t; e < EE; e += 256)
        part += (tv0[e] + tv1[e] + g_wvec[e]) * pp[e];
    float c1000 = (bsum(part, red, t) + g_c0[0]) * NSCALE;
    __syncthreads();

    float m = -3.4e38f;
    for (int k = t; k <= RR; k += 256) {
        float v = (k < RR) ? ((s0[k] + s1[k]) * NSCALE + g_cs[k]) : c1000;
        m = fmaxf(m, v);
    }
    m = bmax(m, red, t);
    __syncthreads();

    float se = 0.f, sv = 0.f;
    for (int k = t; k <= RR; k += 256) {
        float raw = (k < RR) ? ((s0[k] + s1[k]) * NSCALE + g_cs[k]) : c1000;
        float v = raw - m;
        float ev = expf(v);
        se += ev; sv += ev * v;
    }
    float Z = bsum(se, red, t);
    __syncthreads();
    float S2 = bsum(sv, red, t);
    if (t == 0) {
        loss_out[b * SS + lossidx] = logf(Z) - S2 / Z;
        g_pp[b] = expf(c1000 - m) / Z;
    }

    float* pr = &g_probp[(size_t)b * 1024];
    for (int k = t; k < 1024; k += 256) {
        if (k < RR) {
            float raw = (s0[k] + s1[k]) * NSCALE + g_cs[k];
            pr[k] = expf(raw - m) / Z;
        } else {
            pr[k] = 0.f;
        }
    }
    if (scores_out) {
        for (int k = t; k <= RR; k += 256) {
            float raw = (k < RR) ? ((s0[k] + s1[k]) * NSCALE + g_cs[k]) : c1000;
            scores_out[(size_t)b * (RR + 1) + k] = raw;
        }
    }
    if (t == 0 && do_book) {
        int sel = g_sel[b];
        int* ord = &g_ord[b * SS];
        float* ps = &g_pscore[b * SS];
        int slot = ord[sel];
        g_dslot[b] = slot;
        g_src[b * SS + slot] = -1;
        for (int i = sel + 1; i < L - 1; i++) { ord[i] = ord[i + 1]; ps[i] = ps[i + 1]; }
    }
}

__device__ void ph_h1fin(int b, const float* __restrict__ b_ih,
                         const float* __restrict__ b_hh, float* sgi)
{
    int t = threadIdx.x;
    int slot = g_dslot[b];
    float pp = g_pp[b];
    float* orow = &g_gi[((size_t)b * SS + slot) * G3];
    const float* m0 = &g_gm4[0][(size_t)b * G3];
    const float* m1 = &g_gm4[1][(size_t)b * G3];
    const float* m2 = &g_gm4[2][(size_t)b * G3];
    const float* m3 = &g_gm4[3][(size_t)b * G3];
    const float* p0 = &g_gp0[(size_t)b * G3];
    const float* p1 = &g_gp1[(size_t)b * G3];
    for (int e = t; e < G3; e += 256) {
        float v = m0[e] + m1[e] + m2[e] + m3[e] + pp * (p0[e] + p1[e] + b_ih[e]);
        sgi[e] = v;
        orow[e] = v;
    }
    __syncthreads();
    for (int e = t; e < EE; e += 256) {
        float r = sigmf(sgi[e] + b_hh[e]);
        float z = sigmf(sgi[EE + e] + b_hh[EE + e]);
        float n = tanhf(sgi[2 * EE + e] + r * b_hh[2 * EE + e]);
        float h = (1.f - z) * n;
        g_h1[((size_t)b * SS + slot) * EE + e] = h;
        g_newh1[(size_t)b * EE + e] = h;
    }
}

// =================== Phase 1: pairsel -> (scores,tvec | giP) -> softmax ===================
__global__ __launch_bounds__(256, 4) void k_phase1(
    int rnd, int npairs, int zloss, int first, int do_gip,
    int lossidx, int L, int do_book,
    const float* __restrict__ w_fc, const float* __restrict__ b_fc,
    const float* __restrict__ b_hh, const float* __restrict__ W_ih,
    float* __restrict__ loss_out, float* __restrict__ scores_out)
{
    __shared__ SmemU su;
    int bid = blockIdx.x;

    if (bid < BB) {
        ph_pairsel(bid, w_fc, b_fc, b_hh, npairs, zloss, loss_out, first, su.sm);
        chain_signal(&g_cnt1[rnd]);
    } else if (bid < BB + 192) {
        int j = bid - BB;
        if (j >= 96 && !do_gip) return;
        chain_wait(&g_cnt1[rnd], BB);
        if (j < 96) {
            int xt = j % 24, yt = (j / 24) & 1, ks = j / 48;
            if (xt < 16)
                mm_job(g_pair, 512, g_KW, 512, ks ? g_sc1 : g_sc0, RR,
                       0, ks * 256, 16, 1 << 30, xt * 64, yt * 64, su.pp);
            else
                mm_job(g_pair, 512, g_AT, 512, ks ? g_tv1 : g_tv0, EE,
                       0, ks * 256, 16, 1 << 30, (xt - 16) * 64, yt * 64, su.pp);
            chain_signal(&g_cnt2[rnd]);
        } else {
            int j2 = j - 96;
            int xt = j2 % 24, yt = (j2 / 24) & 1, ks = j2 / 48;
            mm_job(g_pair, 512, W_ih, 512, ks ? g_gp1 : g_gp0, G3,
                   0, ks * 256, 16, 1 << 30, xt * 64, yt * 64, su.pp);
        }
    } else {
        int b = bid - (BB + 192);
        chain_wait(&g_cnt2[rnd], 96);
        ph_softmax(b, lossidx, L, do_book, loss_out, scores_out, su.sm.red);
    }
}

// =================== Phase 2: gimix -> h1fin -> ghh ===================
__global__ __launch_bounds__(256, 4) void k_phase2(
    int rnd, const float* __restrict__ b_ih, const float* __restrict__ b_hh,
    const float* __restrict__ W_hh)
{
    __shared__ SmemU su;
    int bid = blockIdx.x;

    if (bid < 192) {
        int xt = bid % 24, yt = (bid / 24) & 1, ks = bid / 48;
        mm_job(g_probp, 1024, GI_emb, G3, g_gm4[ks], G3,
               1, ks * 256, 16, RR, xt * 64, yt * 64, su.pp);
        chain_signal(&g_cnt3[rnd]);
    } else if (bid < 320) {
        int b = bid - 192;
        chain_wait(&g_cnt3[rnd], 192);
        ph_h1fin(b, b_ih, b_hh, su.sgi);
        chain_signal(&g_cnt4[rnd]);
    } else {
        int j = bid - 320;
        chain_wait(&g_cnt4[rnd], BB);
        int xt = j % 24, yt = (j / 24) & 1, ks = j / 48;
        mm_job(g_newh1, 512, W_hh, 512, g_gh[ks], G3,
               0, ks * 128, 8, 1 << 30, xt * 64, yt * 64, su.pp);
    }
}

// ---------------- host ----------------
extern "C" void kernel_launch(void* const* d_in, const int* in_sizes, int n_in,
                              void* d_out, int out_size) {
    const int*   tokens = (const int*)  d_in[0];
    const float* emb    = (const float*)d_in[1];
    const float* W_ih   = (const float*)d_in[2];
    const float* W_hh   = (const float*)d_in[3];
    const float* b_ih   = (const float*)d_in[4];
    const float* b_hh   = (const float*)d_in[5];
    const float* w_fc   = (const float*)d_in[6];
    const float* b_fc   = (const float*)d_in[7];
    const float* Wq     = (const float*)d_in[8];
    const float* bq     = (const float*)d_in[9];
    const float* Wk     = (const float*)d_in[10];
    const float* bk     = (const float*)d_in[11];

    float* out_scores = (float*)d_out;                         // 128 x 1001
    float* out_loss   = (float*)d_out + (size_t)BB * (RR + 1); // 128 x 16

    float *GI, *H1, *GHH, *Krel, *KW, *AT;
    cudaGetSymbolAddress((void**)&GI, GI_emb);
    cudaGetSymbolAddress((void**)&H1, H1_emb);
    cudaGetSymbolAddress((void**)&GHH, GHH_emb);
    cudaGetSymbolAddress((void**)&Krel, g_Krel);
    cudaGetSymbolAddress((void**)&KW, g_KW);
    cudaGetSymbolAddress((void**)&AT, g_AT);

    // ---- init (once per call) ----
    k_init<<<BB, 32>>>(tokens);
    k_tab<<<dim3(24, 16), 256>>>(emb, W_ih, b_ih, GI, RR, G3, G3, 1.f);
    k_h1emb<<<RR, 256>>>(b_hh);
    k_tab<<<dim3(24, 16), 256>>>(H1, W_hh, b_hh, GHH, RR, G3, G3, 1.f);
    k_tab<<<dim3(8, 16), 256>>>(emb, Wk, bk, Krel, RR, EE, EE, 1.f);
    k_gemm_kn<<<dim3(8, 16), 256>>>(Krel, Wq, KW, RR, EE, EE);
    k_cinit<<<125, 256>>>(bq);
    k_gemm_tn<<<dim3(8, 8), 256>>>(Wk, Wq, AT);
    k_wc<<<2, 256>>>(Wq, bq, Wk, bk);

    // ---- 14 merge rounds: 2 launches each ----
    for (int i = 0; i < 14; i++) {
        int L = SS - i;
        k_phase1<<<448, 256>>>(i, L - 1, -1, i == 0, 1, i, L, 1,
                               w_fc, b_fc, b_hh, W_ih, out_loss, NULL);
        k_phase2<<<512, 256>>>(i, b_ih, b_hh, W_hh);
    }
    // ---- final round (L=2) + output attention: one phase1 ----
    k_phase1<<<448, 256>>>(14, 1, 14, 0, 0, 15, 0, 0,
                           w_fc, b_fc, b_hh, W_ih, out_loss, out_scores);
}

// round 16
// speedup vs baseline: 1.1694x; 1.1694x over previous
#include <cuda_runtime.h>
#include <math.h>

#define BB 128
#define SS 16
#define EE 512
#define RR 1000
#define G3 1536
#define NSCALE 0.04419417382415922f

// ---- device scratch (static, no allocations) ----
__device__ float GI_emb[RR * G3];
__device__ float H1_emb[RR * EE];
__device__ float GHH_emb[RR * G3];
__device__ float g_tscr[RR * G3];      // split-K scratch for table GEMMs
__device__ float g_Krel[RR * EE];
__device__ float g_KW[RR * EE];
__device__ float g_cs[RR];
__device__ float g_AT[EE * EE];
__device__ float g_wvec[EE];
__device__ float g_c0[1];

__device__ float g_gi [BB * SS * G3];
__device__ float g_h1 [BB * SS * EE];
__device__ float g_ghh[BB * SS * G3];

__device__ int   g_src [BB * SS];
__device__ int   g_ord [BB * SS];
__device__ int   g_sel [BB];
__device__ int   g_dslot[BB];
__device__ float g_pscore[BB * SS];

__device__ float g_pair [BB * EE];
__device__ float g_newh1[BB * EE];
__device__ float g_probp[BB * 1024];   // padded probs, [1000..1023] = 0
__device__ float g_pp[BB];             // prob of the pair key

// split-K partial buffers
__device__ float g_scp[4][BB * RR];
__device__ float g_tvp[4][BB * EE];
__device__ float g_gp0[BB * G3];
__device__ float g_gp1[BB * G3];
__device__ float g_gm4[4][BB * G3];
__device__ float g_gh[4][BB * G3];

typedef unsigned long long ull;
__device__ __forceinline__ ull pack2(float lo, float hi) {
    ull r; asm("mov.b64 %0, {%1, %2};" : "=l"(r) : "f"(lo), "f"(hi)); return r;
}
__device__ __forceinline__ void unpack2(ull v, float& lo, float& hi) {
    asm("mov.b64 {%0, %1}, %2;" : "=f"(lo), "=f"(hi) : "l"(v));
}
#define FMA2(acc, a, b) asm("fma.rn.f32x2 %0, %1, %2, %0;" : "+l"(acc) : "l"(a), "l"(b))

__device__ __forceinline__ float sigmf(float x) { return 1.0f / (1.0f + expf(-x)); }

__device__ __forceinline__ const float* p_gi(int b, int s) {
    int src = g_src[b * SS + s];
    return (src >= 0) ? &GI_emb[(size_t)src * G3] : &g_gi[((size_t)b * SS + s) * G3];
}
__device__ __forceinline__ const float* p_ghh(int b, int s) {
    int src = g_src[b * SS + s];
    return (src >= 0) ? &GHH_emb[(size_t)src * G3] : &g_ghh[((size_t)b * SS + s) * G3];
}
__device__ __forceinline__ const float* p_h1(int b, int s) {
    int src = g_src[b * SS + s];
    return (src >= 0) ? &H1_emb[(size_t)src * EE] : &g_h1[((size_t)b * SS + s) * EE];
}

__global__ void k_init(const int* __restrict__ tokens) {
    int b = blockIdx.x, t = threadIdx.x;
    if (t < SS) {
        g_ord[b * SS + t] = t;
        g_src[b * SS + t] = tokens[b * SS + t];
    }
}

// ======================================================================
// BEST-MEASURED core: 64x64 tile, 4x4 f32x2 reg tile, packed-A at use,
// ping-pong smem, one sync per k-tile.
// ======================================================================
struct PPBuf {
    float shA[2][16][68];
    float shB[2][16][68];
};

__device__ __forceinline__ void pp_storeA(float (*As)[68], int akg, int am, float4 ra) {
    As[akg*4+0][am] = ra.x; As[akg*4+1][am] = ra.y;
    As[akg*4+2][am] = ra.z; As[akg*4+3][am] = ra.w;
}
__device__ __forceinline__ void pp_compute(float (*As)[68], float (*Bs)[68],
                                           int tx, int ty, ull acc[4][2]) {
#pragma unroll
    for (int kk = 0; kk < 16; kk++) {
        ull b0 = *(const ull*)&Bs[kk][tx*4];
        ull b1 = *(const ull*)&Bs[kk][tx*4+2];
        float4 a = *(const float4*)&As[kk][ty*4];
        ull a0 = pack2(a.x, a.x), a1 = pack2(a.y, a.y);
        ull a2 = pack2(a.z, a.z), a3 = pack2(a.w, a.w);
        FMA2(acc[0][0], a0, b0); FMA2(acc[0][1], a0, b1);
        FMA2(acc[1][0], a1, b0); FMA2(acc[1][1], a1, b1);
        FMA2(acc[2][0], a2, b0); FMA2(acc[2][1], a2, b1);
        FMA2(acc[3][0], a3, b0); FMA2(acc[3][1], a3, b1);
    }
}

// ======================================================================
// Per-round GEMM phases (split-K partials, raw output, bias in consumers)
// ======================================================================
#define PH_BGA   0   // A=g_pair : xt<16 scores(KW), else tvec(AT);  z = K-slice (4, 8 iters)
#define PH_GIMIX 1   // z<4: probp@GI_emb slices;  z in {4,5}: giP = pair@W_ih slices
#define PH_GHH   2   // A=g_newh1, B=W_hh, z = K-slice (4, 8 iters)

__global__ __launch_bounds__(256) void k_mm(int phase,
    const float* __restrict__ W_ih, const float* __restrict__ W_hh)
{
    __shared__ PPBuf tb;
    int t = threadIdx.x, tx = t & 15, ty = t >> 4;
    int xt = blockIdx.x, yt = blockIdx.y, ks = blockIdx.z;

    const float* A; int lda; const float* W; float* out; int N, wld;
    int kn = 0, kb, NIT = 16, Kmax = 1 << 30;
    if (phase == PH_BGA) {
        A = g_pair; lda = 512; wld = 512; kb = ks * 128; NIT = 8;
        if (xt < 16) { W = g_KW; out = g_scp[ks]; N = RR; }
        else         { W = g_AT; out = g_tvp[ks]; N = EE; xt -= 16; }
    } else if (phase == PH_GIMIX) {
        if (ks < 4) {
            A = g_probp; lda = 1024; W = GI_emb; wld = G3;
            out = g_gm4[ks]; N = G3; kn = 1; kb = ks * 256; Kmax = RR;
        } else {
            A = g_pair; lda = 512; W = W_ih; wld = 512;
            out = (ks == 5) ? g_gp1 : g_gp0; N = G3; kb = (ks - 4) * 256;
        }
    } else {
        A = g_newh1; lda = 512; W = W_hh; wld = 512;
        out = g_gh[ks]; N = G3; kb = ks * 128; NIT = 8;
    }
    int col0 = xt * 64, row0 = yt * 64;

    ull acc[4][2];
#pragma unroll
    for (int i = 0; i < 4; i++) { acc[i][0] = 0ULL; acc[i][1] = 0ULL; }

    int am = t >> 2, akg = t & 3;
    int gmA = row0 + am;
    int bn = t >> 2, bkg = t & 3;       // kn==0 (W is N-row-major)
    int kkB = t >> 4, ngB = t & 15;     // kn==1 (W is K-row-major)

    float4 ra = *(const float4*)&A[(size_t)gmA * lda + kb + akg * 4];
    float4 rb;
    if (kn == 0) {
        int gn = col0 + bn;
        rb = (gn < N) ? *(const float4*)&W[(size_t)gn * wld + kb + bkg * 4]
                      : make_float4(0.f, 0.f, 0.f, 0.f);
    } else {
        int k = kb + kkB;
        rb = (k < Kmax) ? *(const float4*)&W[(size_t)k * wld + col0 + ngB * 4]
                        : make_float4(0.f, 0.f, 0.f, 0.f);
    }
    pp_storeA(tb.shA[0], akg, am, ra);
    if (kn == 0) pp_storeA(tb.shB[0], bkg, bn, rb);
    else         *(float4*)&tb.shB[0][kkB][ngB * 4] = rb;
    __syncthreads();

    for (int it = 0; it < NIT; it++) {
        int cur = it & 1;
        if (it < NIT - 1) {
            int k0 = kb + (it + 1) * 16;
            ra = *(const float4*)&A[(size_t)gmA * lda + k0 + akg * 4];
            if (kn == 0) {
                int gn = col0 + bn;
                rb = (gn < N) ? *(const float4*)&W[(size_t)gn * wld + k0 + bkg * 4]
                              : make_float4(0.f, 0.f, 0.f, 0.f);
            } else {
                int k = k0 + kkB;
                rb = (k < Kmax) ? *(const float4*)&W[(size_t)k * wld + col0 + ngB * 4]
                                : make_float4(0.f, 0.f, 0.f, 0.f);
            }
        }
        pp_compute(tb.shA[cur], tb.shB[cur], tx, ty, acc);
        if (it < NIT - 1) {
            int nxt = 1 - cur;
            pp_storeA(tb.shA[nxt], akg, am, ra);
            if (kn == 0) pp_storeA(tb.shB[nxt], bkg, bn, rb);
            else         *(float4*)&tb.shB[nxt][kkB][ngB * 4] = rb;
        }
        __syncthreads();
    }
#pragma unroll
    for (int i = 0; i < 4; i++) {
        int gm = row0 + ty * 4 + i;
        float* orow = out + (size_t)gm * N;
#pragma unroll
        for (int j = 0; j < 2; j++) {
            float lo, hi;
            unpack2(acc[i][j], lo, hi);
            int c = col0 + tx * 4 + j * 2;
            if (c < N)     orow[c]     = lo;
            if (c + 1 < N) orow[c + 1] = hi;
        }
    }
}

// ============ init table GEMM, full-K with bias (Krel)
__global__ __launch_bounds__(256) void k_tab(
    const float* __restrict__ A, const float* __restrict__ W,
    const float* __restrict__ bias, float* __restrict__ out,
    int M, int N, int ldout, float scale)
{
    __shared__ PPBuf tb;
    int t = threadIdx.x, tx = t & 15, ty = t >> 4;
    int col0 = blockIdx.x * 64, row0 = blockIdx.y * 64;

    ull acc[4][2];
#pragma unroll
    for (int i = 0; i < 4; i++) { acc[i][0] = 0ULL; acc[i][1] = 0ULL; }

    int am = t >> 2, akg = t & 3;
    int gmA = row0 + am, gnB = col0 + am;

    float4 ra = (gmA < M) ? *(const float4*)&A[(size_t)gmA * 512 + akg * 4]
                          : make_float4(0.f, 0.f, 0.f, 0.f);
    float4 rb = (gnB < N) ? *(const float4*)&W[(size_t)gnB * 512 + akg * 4]
                          : make_float4(0.f, 0.f, 0.f, 0.f);
    pp_storeA(tb.shA[0], akg, am, ra);
    pp_storeA(tb.shB[0], akg, am, rb);
    __syncthreads();

    for (int it = 0; it < 32; it++) {
        int cur = it & 1;
        if (it < 31) {
            int k0 = (it + 1) * 16;
            ra = (gmA < M) ? *(const float4*)&A[(size_t)gmA * 512 + k0 + akg * 4]
                           : make_float4(0.f, 0.f, 0.f, 0.f);
            rb = (gnB < N) ? *(const float4*)&W[(size_t)gnB * 512 + k0 + akg * 4]
                           : make_float4(0.f, 0.f, 0.f, 0.f);
        }
        pp_compute(tb.shA[cur], tb.shB[cur], tx, ty, acc);
        if (it < 31) {
            int nxt = 1 - cur;
            pp_storeA(tb.shA[nxt], akg, am, ra);
            pp_storeA(tb.shB[nxt], akg, am, rb);
        }
        __syncthreads();
    }
#pragma unroll
    for (int i = 0; i < 4; i++) {
        int gm = row0 + ty * 4 + i;
        if (gm >= M) continue;
        float* orow = out + (size_t)gm * (size_t)ldout;
#pragma unroll
        for (int j = 0; j < 2; j++) {
            float lo, hi;
            unpack2(acc[i][j], lo, hi);
            int c = col0 + tx * 4 + j * 2;
            if (c < N)     orow[c]     = lo * scale + (bias ? bias[c]     : 0.f);
            if (c + 1 < N) orow[c + 1] = hi * scale + (bias ? bias[c + 1] : 0.f);
        }
    }
}

// ============ init table GEMM, split-K2, raw partials (GI / GHH tables)
__global__ __launch_bounds__(256) void k_tab2(
    const float* __restrict__ A, const float* __restrict__ W,
    float* __restrict__ out0, float* __restrict__ out1,
    int M, int N)
{
    __shared__ PPBuf tb;
    int t = threadIdx.x, tx = t & 15, ty = t >> 4;
    int col0 = blockIdx.x * 64, row0 = blockIdx.y * 64;
    int kb = blockIdx.z * 256;
    float* out = blockIdx.z ? out1 : out0;

    ull acc[4][2];
#pragma unroll
    for (int i = 0; i < 4; i++) { acc[i][0] = 0ULL; acc[i][1] = 0ULL; }

    int am = t >> 2, akg = t & 3;
    int gmA = row0 + am, gnB = col0 + am;

    float4 ra = (gmA < M) ? *(const float4*)&A[(size_t)gmA * 512 + kb + akg * 4]
                          : make_float4(0.f, 0.f, 0.f, 0.f);
    float4 rb = (gnB < N) ? *(const float4*)&W[(size_t)gnB * 512 + kb + akg * 4]
                          : make_float4(0.f, 0.f, 0.f, 0.f);
    pp_storeA(tb.shA[0], akg, am, ra);
    pp_storeA(tb.shB[0], akg, am, rb);
    __syncthreads();

    for (int it = 0; it < 16; it++) {
        int cur = it & 1;
        if (it < 15) {
            int k0 = kb + (it + 1) * 16;
            ra = (gmA < M) ? *(const float4*)&A[(size_t)gmA * 512 + k0 + akg * 4]
                           : make_float4(0.f, 0.f, 0.f, 0.f);
            rb = (gnB < N) ? *(const float4*)&W[(size_t)gnB * 512 + k0 + akg * 4]
                           : make_float4(0.f, 0.f, 0.f, 0.f);
        }
        pp_compute(tb.shA[cur], tb.shB[cur], tx, ty, acc);
        if (it < 15) {
            int nxt = 1 - cur;
            pp_storeA(tb.shA[nxt], akg, am, ra);
            pp_storeA(tb.shB[nxt], akg, am, rb);
        }
        __syncthreads();
    }
#pragma unroll
    for (int i = 0; i < 4; i++) {
        int gm = row0 + ty * 4 + i;
        if (gm >= M) continue;
        float* orow = out + (size_t)gm * (size_t)N;
#pragma unroll
        for (int j = 0; j < 2; j++) {
            float lo, hi;
            unpack2(acc[i][j], lo, hi);
            int c = col0 + tx * 4 + j * 2;
            if (c < N)     orow[c]     = lo;
            if (c + 1 < N) orow[c + 1] = hi;
        }
    }
}

// ============ KW = Krel @ Wq (B K-row-major), init-only
__global__ __launch_bounds__(256) void k_gemm_kn(
    const float* __restrict__ A, const float* __restrict__ B,
    float* __restrict__ out, int M, int N, int ldb)
{
    __shared__ PPBuf tb;
    int t = threadIdx.x, tx = t & 15, ty = t >> 4;
    int col0 = blockIdx.x * 64, row0 = blockIdx.y * 64;
    ull acc[4][2];
#pragma unroll
    for (int i = 0; i < 4; i++) { acc[i][0] = 0ULL; acc[i][1] = 0ULL; }

    int am = t >> 2, akg = t & 3;
    int gmA = row0 + am;
    int kkB = t >> 4, ngB = t & 15;

    float4 ra = (gmA < M) ? *(const float4*)&A[(size_t)gmA * 512 + akg * 4]
                          : make_float4(0.f,0.f,0.f,0.f);
    float4 rb = *(const float4*)&B[(size_t)kkB * ldb + col0 + ngB * 4];
    pp_storeA(tb.shA[0], akg, am, ra);
    *(float4*)&tb.shB[0][kkB][ngB * 4] = rb;
    __syncthreads();

    for (int it = 0; it < 32; it++) {
        int cur = it & 1;
        if (it < 31) {
            int k0 = (it + 1) * 16;
            ra = (gmA < M) ? *(const float4*)&A[(size_t)gmA * 512 + k0 + akg * 4]
                           : make_float4(0.f,0.f,0.f,0.f);
            rb = *(const float4*)&B[(size_t)(k0 + kkB) * ldb + col0 + ngB * 4];
        }
        pp_compute(tb.shA[cur], tb.shB[cur], tx, ty, acc);
        if (it < 31) {
            int nxt = 1 - cur;
            pp_storeA(tb.shA[nxt], akg, am, ra);
            *(float4*)&tb.shB[nxt][kkB][ngB * 4] = rb;
        }
        __syncthreads();
    }
#pragma unroll
    for (int i = 0; i < 4; i++) {
        int gm = row0 + ty * 4 + i;
        if (gm >= M) continue;
#pragma unroll
        for (int j = 0; j < 2; j++) {
            float lo, hi;
            unpack2(acc[i][j], lo, hi);
            int c = col0 + tx * 4 + j * 2;
            if (c < N)     out[(size_t)gm * N + c]     = lo;
            if (c + 1 < N) out[(size_t)gm * N + c + 1] = hi;
        }
    }
}

// ============ AT[m][n] = sum_k Wk[k][m] * Wq[k][n]  (both K-row-major), init-only
__global__ __launch_bounds__(256) void k_gemm_tn(
    const float* __restrict__ P, const float* __restrict__ Q, float* __restrict__ out)
{
    __shared__ PPBuf tb;
    int t = threadIdx.x, tx = t & 15, ty = t >> 4;
    int col0 = blockIdx.x * 64, row0 = blockIdx.y * 64;
    ull acc[4][2];
#pragma unroll
    for (int i = 0; i < 4; i++) { acc[i][0] = 0ULL; acc[i][1] = 0ULL; }
    int kk0 = t >> 4, g = t & 15;

    float4 ra = *(const float4*)&P[(size_t)kk0 * 512 + row0 + g * 4];
    float4 rb = *(const float4*)&Q[(size_t)kk0 * 512 + col0 + g * 4];
    *(float4*)&tb.shA[0][kk0][g * 4] = ra;
    *(float4*)&tb.shB[0][kk0][g * 4] = rb;
    __syncthreads();

    for (int it = 0; it < 32; it++) {
        int cur = it & 1;
        if (it < 31) {
            int k0 = (it + 1) * 16;
            ra = *(const float4*)&P[(size_t)(k0 + kk0) * 512 + row0 + g * 4];
            rb = *(const float4*)&Q[(size_t)(k0 + kk0) * 512 + col0 + g * 4];
        }
        pp_compute(tb.shA[cur], tb.shB[cur], tx, ty, acc);
        if (it < 31) {
            int nxt = 1 - cur;
            *(float4*)&tb.shA[nxt][kk0][g * 4] = ra;
            *(float4*)&tb.shB[nxt][kk0][g * 4] = rb;
        }
        __syncthreads();
    }
#pragma unroll
    for (int i = 0; i < 4; i++) {
        int gm = row0 + ty * 4 + i;
#pragma unroll
        for (int j = 0; j < 2; j++) {
            float lo, hi;
            unpack2(acc[i][j], lo, hi);
            int c = col0 + tx * 4 + j * 2;
            out[(size_t)gm * 512 + c]     = lo;
            out[(size_t)gm * 512 + c + 1] = hi;
        }
    }
}

__global__ void k_wc(const float* __restrict__ Wq, const float* __restrict__ bq,
                     const float* __restrict__ Wk, const float* __restrict__ bk) {
    __shared__ float red[256];
    int t = threadIdx.x;
    int i = blockIdx.x * 256 + t;
    float acc = 0.f;
    for (int n = 0; n < EE; n++)
        acc += Wq[(size_t)n * EE + i] * bk[n] + Wk[(size_t)n * EE + i] * bq[n];
    g_wvec[i] = acc;
    if (blockIdx.x == 0) {
        float p = 0.f;
        for (int n = t; n < EE; n += 256) p += bq[n] * bk[n];
        red[t] = p; __syncthreads();
        for (int s = 128; s > 0; s >>= 1) { if (t < s) red[t] += red[t + s]; __syncthreads(); }
        if (t == 0) g_c0[0] = red[0];
    }
}

// h1emb: finalize GI = GIa + GIb + b_ih (write), then H1 from it.
__global__ void k_h1emb(const float* __restrict__ b_ih, const float* __restrict__ b_hh) {
    int tk = blockIdx.x;
    float* gi = &GI_emb[(size_t)tk * G3];
    const float* gs = &g_tscr[(size_t)tk * G3];
    for (int e = threadIdx.x; e < G3; e += blockDim.x)
        gi[e] = gi[e] + gs[e] + b_ih[e];
    __syncthreads();
    for (int e = threadIdx.x; e < EE; e += blockDim.x) {
        float r = sigmf(gi[e] + b_hh[e]);
        float z = sigmf(gi[EE + e] + b_hh[EE + e]);
        float n = tanhf(gi[2 * EE + e] + r * b_hh[2 * EE + e]);
        H1_emb[(size_t)tk * EE + e] = (1.f - z) * n;
    }
}

// finalize GHH = GHHa + GHHb + b_hh
__global__ void k_add(const float* __restrict__ b_hh) {
    int tk = blockIdx.x;
    float* o = &GHH_emb[(size_t)tk * G3];
    const float* s = &g_tscr[(size_t)tk * G3];
    for (int e = threadIdx.x; e < G3; e += blockDim.x)
        o[e] = o[e] + s[e] + b_hh[e];
}

__global__ void k_cinit(const float* __restrict__ bq) {
    int r = blockIdx.x * 8 + (threadIdx.x >> 5);
    int lane = threadIdx.x & 31;
    if (r >= RR) return;
    float s = 0.f;
    for (int e = lane; e < EE; e += 32) s += bq[e] * g_Krel[(size_t)r * EE + e];
#pragma unroll
    for (int off = 16; off > 0; off >>= 1) s += __shfl_down_sync(0xffffffffu, s, off);
    if (lane == 0) g_cs[r] = NSCALE * s;
}

// =================== round-phase kernels ===================

__device__ __forceinline__ float pair_elem(const float* gi, const float* gh,
                                           const float* h1, int e) {
    float r = sigmf(gi[e] + gh[e]);
    float z = sigmf(gi[EE + e] + gh[EE + e]);
    float n = tanhf(gi[2 * EE + e] + r * gh[2 * EE + e]);
    return (1.f - z) * n + z * h1[e];
}

__global__ void k_pairsel(const float* __restrict__ wfc, const float* __restrict__ bfc,
                          const float* __restrict__ b_hh,
                          int npairs, int zloss, float* __restrict__ loss_out, int first) {
    int b = blockIdx.x, t = threadIdx.x;
    int w = t >> 5, lane = t & 31;
    __shared__ int sord[SS];
    __shared__ float sps[SS];
    __shared__ int sbestj;

    // finalize previous round's ghh partials into g_ghh[b][prev_dslot]
    if (!first) {
        int slot = g_dslot[b];
        float* orow = &g_ghh[((size_t)b * SS + slot) * G3];
        const float* gA = &g_gh[0][(size_t)b * G3];
        const float* gB = &g_gh[1][(size_t)b * G3];
        const float* gC = &g_gh[2][(size_t)b * G3];
        const float* gD = &g_gh[3][(size_t)b * G3];
        for (int e = t; e < G3; e += 256)
            orow[e] = gA[e] + gB[e] + gC[e] + gD[e] + b_hh[e];
        __syncthreads();
    }

    if (t < SS) {
        sord[t] = g_ord[b * SS + t];
        sps[t]  = g_pscore[b * SS + t];
    }
    int prev_sel = g_sel[b];
    __syncthreads();

    int j0 = -1, j1 = -1;
    if (first) {
        j0 = w;  j1 = w + 8;
        if (j0 >= npairs) j0 = -1;
        if (j1 >= npairs) j1 = -1;
    } else {
        int cnt = 0, jj[2];
        if (prev_sel - 1 >= 0 && prev_sel - 1 < npairs) jj[cnt++] = prev_sel - 1;
        if (prev_sel >= 0 && prev_sel < npairs)         jj[cnt++] = prev_sel;
        if (w < cnt) j0 = jj[w];
    }
#pragma unroll
    for (int rep = 0; rep < 2; rep++) {
        int j = (rep == 0) ? j0 : j1;
        if (j >= 0) {
            const float* gi = p_gi(b, sord[j + 1]);
            const float* gh = p_ghh(b, sord[j]);
            const float* h1 = p_h1(b, sord[j]);
            float s = 0.f;
            for (int e = lane; e < EE; e += 32)
                s += pair_elem(gi, gh, h1, e) * wfc[e];
#pragma unroll
            for (int off = 16; off > 0; off >>= 1)
                s += __shfl_down_sync(0xffffffffu, s, off);
            if (lane == 0) {
                float sc = sigmf(s + bfc[0]);
                sps[j] = sc;
                g_pscore[b * SS + j] = sc;
            }
        }
    }
    __syncthreads();

    if (t == 0) {
        int bj = 0; float bs = sps[0];
        for (int j = 1; j < npairs; j++)
            if (sps[j] > bs) { bs = sps[j]; bj = j; }
        sbestj = bj;
        g_sel[b] = bj;
        if (zloss >= 0) loss_out[b * SS + zloss] = 0.f;
    }
    __syncthreads();
    int j = sbestj;
    const float* gi = p_gi(b, sord[j + 1]);
    const float* gh = p_ghh(b, sord[j]);
    const float* h1 = p_h1(b, sord[j]);
    for (int e = t; e < EE; e += 256)
        g_pair[(size_t)b * EE + e] = pair_elem(gi, gh, h1, e);
}

__device__ __forceinline__ float bsum(float v, float* red, int t) {
    red[t] = v; __syncthreads();
    for (int s = 128; s > 0; s >>= 1) { if (t < s) red[t] += red[t + s]; __syncthreads(); }
    return red[0];
}
__device__ __forceinline__ float bmax(float v, float* red, int t) {
    red[t] = v; __syncthreads();
    for (int s = 128; s > 0; s >>= 1) { if (t < s) red[t] = fmaxf(red[t], red[t + s]); __syncthreads(); }
    return red[0];
}

__global__ void k_softmax(int lossidx, int L, int do_book,
                          float* __restrict__ loss_out, float* __restrict__ scores_out) {
    int b = blockIdx.x, t = threadIdx.x;
    __shared__ float red[256];
    const float* pp  = &g_pair[(size_t)b * EE];
    const float* t0 = &g_tvp[0][(size_t)b * EE];
    const float* t1 = &g_tvp[1][(size_t)b * EE];
    const float* t2 = &g_tvp[2][(size_t)b * EE];
    const float* t3 = &g_tvp[3][(size_t)b * EE];
    const float* s0 = &g_scp[0][(size_t)b * RR];
    const float* s1 = &g_scp[1][(size_t)b * RR];
    const float* s2 = &g_scp[2][(size_t)b * RR];
    const float* s3 = &g_scp[3][(size_t)b * RR];

    float part = 0.f;
    for (int e = t; e < EE; e += 256)
        part += (t0[e] + t1[e] + t2[e] + t3[e] + g_wvec[e]) * pp[e];
    float c1000 = (bsum(part, red, t) + g_c0[0]) * NSCALE;
    __syncthreads();

    float m = -3.4e38f;
    for (int k = t; k <= RR; k += 256) {
        float v = (k < RR) ? ((s0[k] + s1[k] + s2[k] + s3[k]) * NSCALE + g_cs[k]) : c1000;
        m = fmaxf(m, v);
    }
    m = bmax(m, red, t);
    __syncthreads();

    float se = 0.f, sv = 0.f;
    for (int k = t; k <= RR; k += 256) {
        float raw = (k < RR) ? ((s0[k] + s1[k] + s2[k] + s3[k]) * NSCALE + g_cs[k]) : c1000;
        float v = raw - m;
        float ev = expf(v);
        se += ev; sv += ev * v;
    }
    float Z = bsum(se, red, t);
    __syncthreads();
    float S2 = bsum(sv, red, t);
    if (t == 0) {
        loss_out[b * SS + lossidx] = logf(Z) - S2 / Z;
        g_pp[b] = expf(c1000 - m) / Z;
    }

    float* pr = &g_probp[(size_t)b * 1024];
    for (int k = t; k < 1024; k += 256) {
        if (k < RR) {
            float raw = (s0[k] + s1[k] + s2[k] + s3[k]) * NSCALE + g_cs[k];
            pr[k] = expf(raw - m) / Z;
        } else {
            pr[k] = 0.f;
        }
    }
    if (scores_out) {
        for (int k = t; k <= RR; k += 256) {
            float raw = (k < RR) ? ((s0[k] + s1[k] + s2[k] + s3[k]) * NSCALE + g_cs[k]) : c1000;
            scores_out[(size_t)b * (RR + 1) + k] = raw;
        }
    }
    if (t == 0 && do_book) {
        int sel = g_sel[b];
        int* ord = &g_ord[b * SS];
        float* ps = &g_pscore[b * SS];
        int slot = ord[sel];
        g_dslot[b] = slot;
        g_src[b * SS + slot] = -1;
        for (int i = sel + 1; i < L - 1; i++) { ord[i] = ord[i + 1]; ps[i] = ps[i + 1]; }
    }
}

// finalize gi (sum 4 gimix partials + pp*(giP partials + b_ih)), scatter, compute h1
__global__ void k_h1fin(const float* __restrict__ b_ih, const float* __restrict__ b_hh) {
    __shared__ __align__(16) float sgi[G3];
    int b = blockIdx.x, t = threadIdx.x;
    int slot = g_dslot[b];
    float pp = g_pp[b];
    float* orow = &g_gi[((size_t)b * SS + slot) * G3];
    const float* m0 = &g_gm4[0][(size_t)b * G3];
    const float* m1 = &g_gm4[1][(size_t)b * G3];
    const float* m2 = &g_gm4[2][(size_t)b * G3];
    const float* m3 = &g_gm4[3][(size_t)b * G3];
    const float* p0 = &g_gp0[(size_t)b * G3];
    const float* p1 = &g_gp1[(size_t)b * G3];
    for (int e = t; e < G3; e += 256) {
        float v = m0[e] + m1[e] + m2[e] + m3[e] + pp * (p0[e] + p1[e] + b_ih[e]);
        sgi[e] = v;
        orow[e] = v;
    }
    __syncthreads();
    for (int e = t; e < EE; e += 256) {
        float r = sigmf(sgi[e] + b_hh[e]);
        float z = sigmf(sgi[EE + e] + b_hh[EE + e]);
        float n = tanhf(sgi[2 * EE + e] + r * b_hh[2 * EE + e]);
        float h = (1.f - z) * n;
        g_h1[((size_t)b * SS + slot) * EE + e] = h;
        g_newh1[(size_t)b * EE + e] = h;
    }
}

// ---------------- host ----------------
extern "C" void kernel_launch(void* const* d_in, const int* in_sizes, int n_in,
                              void* d_out, int out_size) {
    const int*   tokens = (const int*)  d_in[0];
    const float* emb    = (const float*)d_in[1];
    const float* W_ih   = (const float*)d_in[2];
    const float* W_hh   = (const float*)d_in[3];
    const float* b_ih   = (const float*)d_in[4];
    const float* b_hh   = (const float*)d_in[5];
    const float* w_fc   = (const float*)d_in[6];
    const float* b_fc   = (const float*)d_in[7];
    const float* Wq     = (const float*)d_in[8];
    const float* bq     = (const float*)d_in[9];
    const float* Wk     = (const float*)d_in[10];
    const float* bk     = (const float*)d_in[11];

    float* out_scores = (float*)d_out;                         // 128 x 1001
    float* out_loss   = (float*)d_out + (size_t)BB * (RR + 1); // 128 x 16

    float *GI, *H1, *GHH, *TS, *Krel, *KW, *AT;
    cudaGetSymbolAddress((void**)&GI, GI_emb);
    cudaGetSymbolAddress((void**)&H1, H1_emb);
    cudaGetSymbolAddress((void**)&GHH, GHH_emb);
    cudaGetSymbolAddress((void**)&TS, g_tscr);
    cudaGetSymbolAddress((void**)&Krel, g_Krel);
    cudaGetSymbolAddress((void**)&KW, g_KW);
    cudaGetSymbolAddress((void**)&AT, g_AT);

    // ---- init (once per call) ----
    k_init<<<BB, 32>>>(tokens);
    k_tab2<<<dim3(24, 16, 2), 256>>>(emb, W_ih, GI, TS, RR, G3);
    k_h1emb<<<RR, 256>>>(b_ih, b_hh);                  // GI += TS + b_ih; H1
    k_tab2<<<dim3(24, 16, 2), 256>>>(H1, W_hh, GHH, TS, RR, G3);
    k_add<<<RR, 256>>>(b_hh);                          // GHH += TS + b_hh
    k_tab<<<dim3(8, 16), 256>>>(emb, Wk, bk, Krel, RR, EE, EE, 1.f);
    k_gemm_kn<<<dim3(8, 16), 256>>>(Krel, Wq, KW, RR, EE, EE);
    k_cinit<<<125, 256>>>(bq);
    k_gemm_tn<<<dim3(8, 8), 256>>>(Wk, Wq, AT);
    k_wc<<<2, 256>>>(Wq, bq, Wk, bk);

    // ---- 14 merge rounds ----
    for (int i = 0; i < 14; i++) {
        int L = SS - i;
        k_pairsel<<<BB, 256>>>(w_fc, b_fc, b_hh, L - 1, -1, out_loss, i == 0);
        k_mm<<<dim3(24, 2, 4), 256>>>(PH_BGA, W_ih, W_hh);   // scores + tvec (K4)
        k_softmax<<<BB, 256>>>(i, L, 1, out_loss, NULL);
        k_mm<<<dim3(24, 2, 6), 256>>>(PH_GIMIX, W_ih, W_hh); // gimix K4 + giP K2
        k_h1fin<<<BB, 256>>>(b_ih, b_hh);
        k_mm<<<dim3(24, 2, 4), 256>>>(PH_GHH, W_ih, W_hh);   // ghh K4
    }
    // ---- final round (L=2) + output attention ----
    k_pairsel<<<BB, 256>>>(w_fc, b_fc, b_hh, 1, 14, out_loss, 0);
    k_mm<<<dim3(24, 2, 4), 256>>>(PH_BGA, W_ih, W_hh);       // scores + tvec only
    k_softmax<<<BB, 256>>>(15, 0, 0, out_loss, out_scores);
}